// round 5
// baseline (speedup 1.0000x reference)
#include <cuda_runtime.h>
#include <math.h>

// ----------------------------------------------------------------------------
// Problem constants
// ----------------------------------------------------------------------------
#define B_   2
#define T_   2048
#define S_   2048
#define ED_  1024
#define NH_  16
#define HD_  64
#define FF_  4096
#define BT_  (B_ * T_)          // 4096 rows

// ----------------------------------------------------------------------------
// Device scratch (no allocations allowed -> __device__ globals)
// ----------------------------------------------------------------------------
__device__ float g_H [BT_ * ED_];                 // LN output
__device__ float g_Q [BT_ * ED_];
__device__ float g_K [BT_ * ED_];
__device__ float g_V [BT_ * ED_];
__device__ float g_A [BT_ * ED_];                 // attention output (pre-Wo)
__device__ float g_X1[BT_ * ED_];                 // residual after self-attn
__device__ float g_Kt[B_ * NH_ * HD_ * S_];       // K transposed: [bh][d][s]
__device__ float g_F1[BT_ * FF_];                 // FFN hidden
__device__ float g_S [134217728];                 // scores: [bh][T][S] (512 MB)

// ----------------------------------------------------------------------------
// LayerNorm: one block per row of 1024
// ----------------------------------------------------------------------------
__global__ __launch_bounds__(256) void ln_k(const float* __restrict__ x,
                                            const float* __restrict__ g,
                                            const float* __restrict__ b,
                                            float* __restrict__ o) {
    __shared__ float red[8];
    __shared__ float s_mu, s_rstd;
    long base = (long)blockIdx.x * ED_;
    int t = threadIdx.x;
    float4 v = *(const float4*)(x + base + t * 4);

    float s = v.x + v.y + v.z + v.w;
    #pragma unroll
    for (int off = 16; off; off >>= 1) s += __shfl_xor_sync(0xffffffffu, s, off);
    if ((t & 31) == 0) red[t >> 5] = s;
    __syncthreads();
    if (t == 0) {
        float tot = 0.f;
        #pragma unroll
        for (int i = 0; i < 8; i++) tot += red[i];
        s_mu = tot * (1.0f / ED_);
    }
    __syncthreads();
    float mu = s_mu;
    float dx = v.x - mu, dy = v.y - mu, dz = v.z - mu, dw = v.w - mu;
    float ss = dx * dx + dy * dy + dz * dz + dw * dw;
    #pragma unroll
    for (int off = 16; off; off >>= 1) ss += __shfl_xor_sync(0xffffffffu, ss, off);
    __syncthreads();                       // red reuse
    if ((t & 31) == 0) red[t >> 5] = ss;
    __syncthreads();
    if (t == 0) {
        float tot = 0.f;
        #pragma unroll
        for (int i = 0; i < 8; i++) tot += red[i];
        s_rstd = rsqrtf(tot * (1.0f / ED_) + 1e-5f);
    }
    __syncthreads();
    float rstd = s_rstd;
    float4 gv = *(const float4*)(g + t * 4);
    float4 bv = *(const float4*)(b + t * 4);
    float4 ov;
    ov.x = dx * rstd * gv.x + bv.x;
    ov.y = dy * rstd * gv.y + bv.y;
    ov.z = dz * rstd * gv.z + bv.z;
    ov.w = dw * rstd * gv.w + bv.w;
    *(float4*)(o + base + t * 4) = ov;
}

// ----------------------------------------------------------------------------
// Transpose K [b,s,h,d] -> Kt [bh][d][s]
// ----------------------------------------------------------------------------
__global__ __launch_bounds__(256) void transpose_k(const float* __restrict__ K,
                                                   float* __restrict__ Kt) {
    long i = (long)blockIdx.x * 256 + threadIdx.x;  // over 32*64*2048
    int s  = (int)(i & (S_ - 1));
    int d  = (int)((i >> 11) & (HD_ - 1));
    int bh = (int)(i >> 17);
    int h  = bh & (NH_ - 1);
    int b  = bh >> 4;
    Kt[i] = K[((long)(b * T_ + s)) * ED_ + h * HD_ + d];
}

// ----------------------------------------------------------------------------
// Row softmax over length S_ with optional causal mask.
// Grid: (T_, NH_, B_); one block per row. Masked entries written as 0 so the
// PV GEMM can run over the full K range.
// ----------------------------------------------------------------------------
template <bool CAUSAL>
__global__ __launch_bounds__(256) void softmax_k(float* __restrict__ S) {
    __shared__ float red[8];
    __shared__ float s_mx, s_inv;
    int q = blockIdx.x;
    long base = (((long)(blockIdx.z * NH_ + blockIdx.y)) * T_ + q) * (long)S_;
    int valid = CAUSAL ? (q + 1) : S_;
    int t = threadIdx.x;

    float v[8];
    float mx = -3.0e38f;
    #pragma unroll
    for (int i = 0; i < 8; i++) {
        int k = t + i * 256;
        v[i] = S[base + k];
        if (k < valid) mx = fmaxf(mx, v[i]);
    }
    #pragma unroll
    for (int off = 16; off; off >>= 1) mx = fmaxf(mx, __shfl_xor_sync(0xffffffffu, mx, off));
    if ((t & 31) == 0) red[t >> 5] = mx;
    __syncthreads();
    if (t == 0) {
        float m = red[0];
        #pragma unroll
        for (int i = 1; i < 8; i++) m = fmaxf(m, red[i]);
        s_mx = m;
    }
    __syncthreads();
    mx = s_mx;

    float sum = 0.f;
    #pragma unroll
    for (int i = 0; i < 8; i++) {
        int k = t + i * 256;
        v[i] = (k < valid) ? __expf(v[i] - mx) : 0.0f;
        sum += v[i];
    }
    #pragma unroll
    for (int off = 16; off; off >>= 1) sum += __shfl_xor_sync(0xffffffffu, sum, off);
    __syncthreads();
    if ((t & 31) == 0) red[t >> 5] = sum;
    __syncthreads();
    if (t == 0) {
        float tot = 0.f;
        #pragma unroll
        for (int i = 0; i < 8; i++) tot += red[i];
        s_inv = 1.0f / tot;
    }
    __syncthreads();
    float inv = s_inv;
    #pragma unroll
    for (int i = 0; i < 8; i++) {
        int k = t + i * 256;
        S[base + k] = v[i] * inv;
    }
}

// ----------------------------------------------------------------------------
// Tiled SGEMM: C[M,N] = alpha * (A[M,K] @ B[K,N]) (+ bias) (relu) (+ R)
// BM=128, BK=8, 256 threads, per-thread 8 x TN. Batched via blockIdx.z with
// separate (b, h) strides; pass Hdim=1 for non-batched.
// All of M, K multiples of 128/8; N multiple of BN. No bounds checks.
// ----------------------------------------------------------------------------
template <int BN, int TN, bool BIAS, bool RELU, bool RES>
__global__ __launch_bounds__(256) void gemm_k(
    const float* __restrict__ A, const float* __restrict__ Bm,
    const float* __restrict__ bias, const float* __restrict__ R,
    float* __restrict__ C,
    int K, int lda, int ldb, int ldc,
    long sAb, long sAh, long sBb, long sBh, long sCb, long sCh,
    int Hdim, float alpha) {

    int z = blockIdx.z;
    int bb = z / Hdim, hh = z - bb * Hdim;
    A  += bb * sAb + hh * sAh;
    Bm += bb * sBb + hh * sBh;
    C  += bb * sCb + hh * sCh;
    const float* Rp = R;
    if (RES) Rp += bb * sCb + hh * sCh;

    __shared__ float As[8][128];
    __shared__ float Bs[8][BN];

    int t  = threadIdx.x;
    int bm = blockIdx.y * 128;
    int bn = blockIdx.x * BN;
    int ty = t >> 4, tx = t & 15;

    float acc[8][TN];
    #pragma unroll
    for (int i = 0; i < 8; i++)
        #pragma unroll
        for (int j = 0; j < TN; j++) acc[i][j] = 0.f;

    int arow = t >> 1, acol = (t & 1) * 4;
    int brow, bcol;
    if (BN == 128) { brow = t >> 5; bcol = (t & 31) * 4; }
    else           { brow = t >> 4; bcol = (t & 15) * 4; }
    bool bactive = (BN == 128) || (t < 128);

    for (int kt = 0; kt < K; kt += 8) {
        float4 av = *(const float4*)&A[(long)(bm + arow) * lda + kt + acol];
        float4 bv = make_float4(0.f, 0.f, 0.f, 0.f);
        if (bactive) bv = *(const float4*)&Bm[(long)(kt + brow) * ldb + bn + bcol];
        __syncthreads();
        As[acol + 0][arow] = av.x;
        As[acol + 1][arow] = av.y;
        As[acol + 2][arow] = av.z;
        As[acol + 3][arow] = av.w;
        if (bactive) *(float4*)&Bs[brow][bcol] = bv;
        __syncthreads();

        #pragma unroll
        for (int k = 0; k < 8; k++) {
            float4 a0 = *(const float4*)&As[k][ty * 4];
            float4 a1 = *(const float4*)&As[k][64 + ty * 4];
            float ar[8] = {a0.x, a0.y, a0.z, a0.w, a1.x, a1.y, a1.z, a1.w};
            float br[TN];
            float4 b0 = *(const float4*)&Bs[k][tx * 4];
            br[0] = b0.x; br[1] = b0.y; br[2] = b0.z; br[3] = b0.w;
            if (TN == 8) {
                float4 b1 = *(const float4*)&Bs[k][64 + tx * 4];
                br[4] = b1.x; br[5] = b1.y; br[6] = b1.z; br[7] = b1.w;
            }
            #pragma unroll
            for (int i = 0; i < 8; i++)
                #pragma unroll
                for (int j = 0; j < TN; j++) acc[i][j] += ar[i] * br[j];
        }
    }

    #pragma unroll
    for (int i = 0; i < 8; i++) {
        int row = bm + ((i < 4) ? (ty * 4 + i) : (64 + ty * 4 + (i - 4)));
        #pragma unroll
        for (int j = 0; j < TN; j++) {
            int col;
            if (TN == 8) col = bn + ((j < 4) ? (tx * 4 + j) : (64 + tx * 4 + (j - 4)));
            else         col = bn + tx * 4 + j;
            float vv = acc[i][j] * alpha;
            if (BIAS) vv += bias[col];
            if (RELU) vv = fmaxf(vv, 0.f);
            if (RES)  vv += Rp[(long)row * ldc + col];
            C[(long)row * ldc + col] = vv;
        }
    }
}

// ----------------------------------------------------------------------------
// Host orchestration
// ----------------------------------------------------------------------------
extern "C" void kernel_launch(void* const* d_in, const int* in_sizes, int n_in,
                              void* d_out, int out_size) {
    const float* x     = (const float*)d_in[0];
    const float* enc   = (const float*)d_in[1];
    // d_in[2] = tgt_mask (always causal tril; handled analytically)
    const float* sa_wq = (const float*)d_in[3];
    const float* sa_bq = (const float*)d_in[4];
    const float* sa_wk = (const float*)d_in[5];
    const float* sa_bk = (const float*)d_in[6];
    const float* sa_wv = (const float*)d_in[7];
    const float* sa_bv = (const float*)d_in[8];
    const float* sa_wo = (const float*)d_in[9];
    const float* sa_bo = (const float*)d_in[10];
    const float* ca_wq = (const float*)d_in[11];
    const float* ca_bq = (const float*)d_in[12];
    const float* ca_wk = (const float*)d_in[13];
    const float* ca_bk = (const float*)d_in[14];
    const float* ca_wv = (const float*)d_in[15];
    const float* ca_bv = (const float*)d_in[16];
    const float* ca_wo = (const float*)d_in[17];
    const float* ca_bo = (const float*)d_in[18];
    const float* ff_w1 = (const float*)d_in[19];
    const float* ff_b1 = (const float*)d_in[20];
    const float* ff_w2 = (const float*)d_in[21];
    const float* ff_b2 = (const float*)d_in[22];
    const float* ln1g  = (const float*)d_in[23];
    const float* ln1b  = (const float*)d_in[24];
    const float* ln2g  = (const float*)d_in[25];
    const float* ln2b  = (const float*)d_in[26];
    const float* ln3g  = (const float*)d_in[27];
    const float* ln3b  = (const float*)d_in[28];
    float* out = (float*)d_out;

    float *H, *Q, *K, *V, *A, *X1, *Kt, *F1, *S;
    cudaGetSymbolAddress((void**)&H,  g_H);
    cudaGetSymbolAddress((void**)&Q,  g_Q);
    cudaGetSymbolAddress((void**)&K,  g_K);
    cudaGetSymbolAddress((void**)&V,  g_V);
    cudaGetSymbolAddress((void**)&A,  g_A);
    cudaGetSymbolAddress((void**)&X1, g_X1);
    cudaGetSymbolAddress((void**)&Kt, g_Kt);
    cudaGetSymbolAddress((void**)&F1, g_F1);
    cudaGetSymbolAddress((void**)&S,  g_S);

    const float iscale = 0.125f;   // 1/sqrt(64)
    const long sQb = (long)T_ * ED_;            // per-batch stride in Q/K/V/A
    const long sQh = HD_;                       // per-head stride
    const long sKtb = (long)NH_ * HD_ * S_;
    const long sKth = (long)HD_ * S_;
    const long sSb = (long)NH_ * T_ * S_;
    const long sSh = (long)T_ * S_;

    dim3 gProj(ED_ / 128, BT_ / 128, 1);        // (8, 32)
    dim3 gQK(S_ / 128, T_ / 128, B_ * NH_);     // (16, 16, 32)
    dim3 gPV(1, T_ / 128, B_ * NH_);            // (1, 16, 32)
    dim3 gFF1(FF_ / 128, BT_ / 128, 1);         // (32, 32)

    // ---------------- self-attention block ----------------
    ln_k<<<BT_, 256>>>(x, ln1g, ln1b, H);
    gemm_k<128, 8, true, false, false><<<gProj, 256>>>(H, sa_wq, sa_bq, nullptr, Q,
        ED_, ED_, ED_, ED_, 0, 0, 0, 0, 0, 0, 1, 1.0f);
    gemm_k<128, 8, true, false, false><<<gProj, 256>>>(H, sa_wk, sa_bk, nullptr, K,
        ED_, ED_, ED_, ED_, 0, 0, 0, 0, 0, 0, 1, 1.0f);
    gemm_k<128, 8, true, false, false><<<gProj, 256>>>(H, sa_wv, sa_bv, nullptr, V,
        ED_, ED_, ED_, ED_, 0, 0, 0, 0, 0, 0, 1, 1.0f);
    transpose_k<<<(B_ * NH_ * HD_ * S_) / 256, 256>>>(K, Kt);
    gemm_k<128, 8, false, false, false><<<gQK, 256>>>(Q, Kt, nullptr, nullptr, S,
        HD_, ED_, S_, S_, sQb, sQh, sKtb, sKth, sSb, sSh, NH_, iscale);
    softmax_k<true><<<dim3(T_, NH_, B_), 256>>>(S);
    gemm_k<64, 4, false, false, false><<<gPV, 256>>>(S, V, nullptr, nullptr, A,
        S_, S_, ED_, ED_, sSb, sSh, sQb, sQh, sQb, sQh, NH_, 1.0f);
    gemm_k<128, 8, true, false, true><<<gProj, 256>>>(A, sa_wo, sa_bo, x, X1,
        ED_, ED_, ED_, ED_, 0, 0, 0, 0, 0, 0, 1, 1.0f);

    // ---------------- cross-attention block ----------------
    ln_k<<<BT_, 256>>>(X1, ln2g, ln2b, H);
    gemm_k<128, 8, true, false, false><<<gProj, 256>>>(H, ca_wq, ca_bq, nullptr, Q,
        ED_, ED_, ED_, ED_, 0, 0, 0, 0, 0, 0, 1, 1.0f);
    gemm_k<128, 8, true, false, false><<<gProj, 256>>>(enc, ca_wk, ca_bk, nullptr, K,
        ED_, ED_, ED_, ED_, 0, 0, 0, 0, 0, 0, 1, 1.0f);
    gemm_k<128, 8, true, false, false><<<gProj, 256>>>(enc, ca_wv, ca_bv, nullptr, V,
        ED_, ED_, ED_, ED_, 0, 0, 0, 0, 0, 0, 1, 1.0f);
    transpose_k<<<(B_ * NH_ * HD_ * S_) / 256, 256>>>(K, Kt);
    gemm_k<128, 8, false, false, false><<<gQK, 256>>>(Q, Kt, nullptr, nullptr, S,
        HD_, ED_, S_, S_, sQb, sQh, sKtb, sKth, sSb, sSh, NH_, iscale);
    softmax_k<false><<<dim3(T_, NH_, B_), 256>>>(S);
    gemm_k<64, 4, false, false, false><<<gPV, 256>>>(S, V, nullptr, nullptr, A,
        S_, S_, ED_, ED_, sSb, sSh, sQb, sQh, sQb, sQh, NH_, 1.0f);
    gemm_k<128, 8, true, false, true><<<gProj, 256>>>(A, ca_wo, ca_bo, X1, out,
        ED_, ED_, ED_, ED_, 0, 0, 0, 0, 0, 0, 1, 1.0f);

    // ---------------- feed-forward block ----------------
    ln_k<<<BT_, 256>>>(out, ln3g, ln3b, H);
    gemm_k<128, 8, true, true, false><<<gFF1, 256>>>(H, ff_w1, ff_b1, nullptr, F1,
        ED_, ED_, FF_, FF_, 0, 0, 0, 0, 0, 0, 1, 1.0f);
    gemm_k<128, 8, true, false, true><<<gProj, 256>>>(F1, ff_w2, ff_b2, out, out,
        FF_, FF_, ED_, ED_, 0, 0, 0, 0, 0, 0, 1, 1.0f);
}

// round 7
// speedup vs baseline: 2.3831x; 2.3831x over previous
#include <cuda_runtime.h>
#include <math.h>
#include <stdint.h>

// ----------------------------------------------------------------------------
// Problem constants
// ----------------------------------------------------------------------------
#define B_   2
#define T_   2048
#define S_   2048
#define ED_  1024
#define NH_  16
#define HD_  64
#define FF_  4096
#define BT_  (B_ * T_)          // 4096 rows

// ----------------------------------------------------------------------------
// Device scratch (no allocations allowed -> __device__ globals)
// ----------------------------------------------------------------------------
__device__ float g_H [BT_ * ED_];                 // LN output
__device__ float g_Q [BT_ * ED_];
__device__ float g_K [BT_ * ED_];
__device__ float g_V [BT_ * ED_];
__device__ float g_A [BT_ * ED_];                 // attention output (pre-Wo)
__device__ float g_X1[BT_ * ED_];                 // residual after self-attn
__device__ float g_Kt[B_ * NH_ * HD_ * S_];       // K transposed: [bh][d][s]
__device__ float g_F1[BT_ * FF_];                 // FFN hidden
__device__ float g_S [134217728];                 // scores: [bh][T][S] (512 MB)

// ----------------------------------------------------------------------------
// fp32 -> tf32 (round-to-nearest) helper
// ----------------------------------------------------------------------------
__device__ __forceinline__ uint32_t f2tf(float f) {
    uint32_t u;
    asm("cvt.rna.tf32.f32 %0, %1;" : "=r"(u) : "f"(f));
    return u;
}

// ----------------------------------------------------------------------------
// LayerNorm: one block per row of 1024
// ----------------------------------------------------------------------------
__global__ __launch_bounds__(256) void ln_k(const float* __restrict__ x,
                                            const float* __restrict__ g,
                                            const float* __restrict__ b,
                                            float* __restrict__ o) {
    __shared__ float red[8];
    __shared__ float s_mu, s_rstd;
    long base = (long)blockIdx.x * ED_;
    int t = threadIdx.x;
    float4 v = *(const float4*)(x + base + t * 4);

    float s = v.x + v.y + v.z + v.w;
    #pragma unroll
    for (int off = 16; off; off >>= 1) s += __shfl_xor_sync(0xffffffffu, s, off);
    if ((t & 31) == 0) red[t >> 5] = s;
    __syncthreads();
    if (t == 0) {
        float tot = 0.f;
        #pragma unroll
        for (int i = 0; i < 8; i++) tot += red[i];
        s_mu = tot * (1.0f / ED_);
    }
    __syncthreads();
    float mu = s_mu;
    float dx = v.x - mu, dy = v.y - mu, dz = v.z - mu, dw = v.w - mu;
    float ss = dx * dx + dy * dy + dz * dz + dw * dw;
    #pragma unroll
    for (int off = 16; off; off >>= 1) ss += __shfl_xor_sync(0xffffffffu, ss, off);
    __syncthreads();
    if ((t & 31) == 0) red[t >> 5] = ss;
    __syncthreads();
    if (t == 0) {
        float tot = 0.f;
        #pragma unroll
        for (int i = 0; i < 8; i++) tot += red[i];
        s_rstd = rsqrtf(tot * (1.0f / ED_) + 1e-5f);
    }
    __syncthreads();
    float rstd = s_rstd;
    float4 gv = *(const float4*)(g + t * 4);
    float4 bv = *(const float4*)(b + t * 4);
    float4 ov;
    ov.x = dx * rstd * gv.x + bv.x;
    ov.y = dy * rstd * gv.y + bv.y;
    ov.z = dz * rstd * gv.z + bv.z;
    ov.w = dw * rstd * gv.w + bv.w;
    *(float4*)(o + base + t * 4) = ov;
}

// ----------------------------------------------------------------------------
// Transpose K [b,s,h,d] -> Kt [bh][d][s]
// ----------------------------------------------------------------------------
__global__ __launch_bounds__(256) void transpose_k(const float* __restrict__ K,
                                                   float* __restrict__ Kt) {
    long i = (long)blockIdx.x * 256 + threadIdx.x;
    int s  = (int)(i & (S_ - 1));
    int d  = (int)((i >> 11) & (HD_ - 1));
    int bh = (int)(i >> 17);
    int h  = bh & (NH_ - 1);
    int b  = bh >> 4;
    Kt[i] = K[((long)(b * T_ + s)) * ED_ + h * HD_ + d];
}

// ----------------------------------------------------------------------------
// Row softmax over length S_ with optional causal mask.
// Masked entries written as 0 so the PV GEMM can run over the K range.
// ----------------------------------------------------------------------------
template <bool CAUSAL>
__global__ __launch_bounds__(256) void softmax_k(float* __restrict__ S) {
    __shared__ float red[8];
    __shared__ float s_mx, s_inv;
    int q = blockIdx.x;
    long base = (((long)(blockIdx.z * NH_ + blockIdx.y)) * T_ + q) * (long)S_;
    int valid = CAUSAL ? (q + 1) : S_;
    int t = threadIdx.x;

    float v[8];
    float mx = -3.0e38f;
    #pragma unroll
    for (int i = 0; i < 8; i++) {
        int k = t + i * 256;
        v[i] = S[base + k];
        if (k < valid) mx = fmaxf(mx, v[i]);
    }
    #pragma unroll
    for (int off = 16; off; off >>= 1) mx = fmaxf(mx, __shfl_xor_sync(0xffffffffu, mx, off));
    if ((t & 31) == 0) red[t >> 5] = mx;
    __syncthreads();
    if (t == 0) {
        float m = red[0];
        #pragma unroll
        for (int i = 1; i < 8; i++) m = fmaxf(m, red[i]);
        s_mx = m;
    }
    __syncthreads();
    mx = s_mx;

    float sum = 0.f;
    #pragma unroll
    for (int i = 0; i < 8; i++) {
        int k = t + i * 256;
        v[i] = (k < valid) ? __expf(v[i] - mx) : 0.0f;
        sum += v[i];
    }
    #pragma unroll
    for (int off = 16; off; off >>= 1) sum += __shfl_xor_sync(0xffffffffu, sum, off);
    __syncthreads();
    if ((t & 31) == 0) red[t >> 5] = sum;
    __syncthreads();
    if (t == 0) {
        float tot = 0.f;
        #pragma unroll
        for (int i = 0; i < 8; i++) tot += red[i];
        s_inv = 1.0f / tot;
    }
    __syncthreads();
    float inv = s_inv;
    #pragma unroll
    for (int i = 0; i < 8; i++) {
        int k = t + i * 256;
        S[base + k] = v[i] * inv;
    }
}

// ----------------------------------------------------------------------------
// tf32 tensor-core GEMM: C[M,N] = alpha*(A[M,K]@B[K,N]) (+bias)(relu)(+R)
// BM=128, BK=32, 256 threads (8 warps as WARPS_M x WARPS_N).
// Each warp computes WM x WN via m16n8k8 tf32 mma.sync, fp32 accumulate.
// CSKIP: skip blocks fully above the causal diagonal (scores GEMM).
// CLIM:  truncate K loop at bm+BM (PV GEMM with causal-zeroed softmax).
// Batched via blockIdx.z with (b,h) strides; Hdim=1 for plain GEMM.
// All dims multiples of tile sizes; no bounds checks.
// ----------------------------------------------------------------------------
template <int BN, int WARPS_M, int WARPS_N, bool BIAS, bool RELU, bool RES,
          bool CSKIP, bool CLIM>
__global__ __launch_bounds__(256) void mma_gemm(
    const float* __restrict__ A, const float* __restrict__ Bm,
    const float* __restrict__ bias, const float* __restrict__ R,
    float* __restrict__ C,
    int K, int lda, int ldb, int ldc,
    long sAb, long sAh, long sBb, long sBh, long sCb, long sCh,
    int Hdim, float alpha) {

    constexpr int BM = 128, BK = 32;
    constexpr int WM = BM / WARPS_M, WN = BN / WARPS_N;
    constexpr int MI = WM / 16, NI = WN / 8;
    constexpr int ASTR = BK + 4;        // 36 (bank-conflict-free frag loads)
    constexpr int BSTR = BN + 8;        // 136 / 72
    constexpr int NLA = (BM * BK) / (4 * 256);   // 4 float4 per thread
    constexpr int NLB = (BK * BN) / (4 * 256);   // 4 or 2

    int bm = blockIdx.y * BM;
    int bn = blockIdx.x * BN;
    if (CSKIP && bn >= bm + BM) return;          // fully masked score block

    int z = blockIdx.z;
    int bb = z / Hdim, hh = z - bb * Hdim;
    A  += bb * sAb + hh * sAh;
    Bm += bb * sBb + hh * sBh;
    C  += bb * sCb + hh * sCh;
    const float* Rp = R;
    if (RES) Rp += bb * sCb + hh * sCh;

    __shared__ uint32_t As[BM * ASTR];
    __shared__ uint32_t Bs[BK * BSTR];

    int t = threadIdx.x, lane = t & 31, warp = t >> 5;
    int wm = warp / WARPS_N, wn = warp % WARPS_N;

    int Klim = CLIM ? (bm + BM) : K;

    float4 aR[NLA], bR[NLB];

    // prefetch k-tile 0
    #pragma unroll
    for (int i = 0; i < NLA; i++) {
        int j = t + i * 256; int ar = j >> 3, ac = (j & 7) * 4;
        aR[i] = *(const float4*)&A[(long)(bm + ar) * lda + ac];
    }
    #pragma unroll
    for (int i = 0; i < NLB; i++) {
        int j = t + i * 256;
        int br = (BN == 128) ? (j >> 5) : (j >> 4);
        int bc = ((BN == 128) ? (j & 31) : (j & 15)) * 4;
        bR[i] = *(const float4*)&Bm[(long)br * ldb + bn + bc];
    }
    #pragma unroll
    for (int i = 0; i < NLA; i++) {
        int j = t + i * 256; int ar = j >> 3, ac = (j & 7) * 4;
        uint4 u = make_uint4(f2tf(aR[i].x), f2tf(aR[i].y), f2tf(aR[i].z), f2tf(aR[i].w));
        *(uint4*)&As[ar * ASTR + ac] = u;
    }
    #pragma unroll
    for (int i = 0; i < NLB; i++) {
        int j = t + i * 256;
        int br = (BN == 128) ? (j >> 5) : (j >> 4);
        int bc = ((BN == 128) ? (j & 31) : (j & 15)) * 4;
        uint4 u = make_uint4(f2tf(bR[i].x), f2tf(bR[i].y), f2tf(bR[i].z), f2tf(bR[i].w));
        *(uint4*)&Bs[br * BSTR + bc] = u;
    }
    __syncthreads();

    float acc[MI][NI][4];
    #pragma unroll
    for (int mi = 0; mi < MI; mi++)
        #pragma unroll
        for (int ni = 0; ni < NI; ni++)
            #pragma unroll
            for (int c = 0; c < 4; c++) acc[mi][ni][c] = 0.f;

    for (int kt = BK;; kt += BK) {
        bool more = kt < Klim;
        if (more) {
            #pragma unroll
            for (int i = 0; i < NLA; i++) {
                int j = t + i * 256; int ar = j >> 3, ac = (j & 7) * 4;
                aR[i] = *(const float4*)&A[(long)(bm + ar) * lda + kt + ac];
            }
            #pragma unroll
            for (int i = 0; i < NLB; i++) {
                int j = t + i * 256;
                int br = (BN == 128) ? (j >> 5) : (j >> 4);
                int bc = ((BN == 128) ? (j & 31) : (j & 15)) * 4;
                bR[i] = *(const float4*)&Bm[(long)(kt + br) * ldb + bn + bc];
            }
        }

        #pragma unroll
        for (int ks = 0; ks < 4; ks++) {
            int k0 = ks * 8;
            uint32_t af[MI][4], bf[NI][2];
            #pragma unroll
            for (int mi = 0; mi < MI; mi++) {
                int r0 = wm * WM + mi * 16 + (lane >> 2);
                int kk = k0 + (lane & 3);
                af[mi][0] = As[r0 * ASTR + kk];
                af[mi][1] = As[(r0 + 8) * ASTR + kk];
                af[mi][2] = As[r0 * ASTR + kk + 4];
                af[mi][3] = As[(r0 + 8) * ASTR + kk + 4];
            }
            #pragma unroll
            for (int ni = 0; ni < NI; ni++) {
                int c0 = wn * WN + ni * 8 + (lane >> 2);
                int kk = k0 + (lane & 3);
                bf[ni][0] = Bs[kk * BSTR + c0];
                bf[ni][1] = Bs[(kk + 4) * BSTR + c0];
            }
            #pragma unroll
            for (int mi = 0; mi < MI; mi++)
                #pragma unroll
                for (int ni = 0; ni < NI; ni++)
                    asm volatile(
                        "mma.sync.aligned.m16n8k8.row.col.f32.tf32.tf32.f32 "
                        "{%0,%1,%2,%3},{%4,%5,%6,%7},{%8,%9},{%0,%1,%2,%3};"
                        : "+f"(acc[mi][ni][0]), "+f"(acc[mi][ni][1]),
                          "+f"(acc[mi][ni][2]), "+f"(acc[mi][ni][3])
                        : "r"(af[mi][0]), "r"(af[mi][1]), "r"(af[mi][2]), "r"(af[mi][3]),
                          "r"(bf[ni][0]), "r"(bf[ni][1]));
        }
        if (!more) break;
        __syncthreads();
        #pragma unroll
        for (int i = 0; i < NLA; i++) {
            int j = t + i * 256; int ar = j >> 3, ac = (j & 7) * 4;
            uint4 u = make_uint4(f2tf(aR[i].x), f2tf(aR[i].y), f2tf(aR[i].z), f2tf(aR[i].w));
            *(uint4*)&As[ar * ASTR + ac] = u;
        }
        #pragma unroll
        for (int i = 0; i < NLB; i++) {
            int j = t + i * 256;
            int br = (BN == 128) ? (j >> 5) : (j >> 4);
            int bc = ((BN == 128) ? (j & 31) : (j & 15)) * 4;
            uint4 u = make_uint4(f2tf(bR[i].x), f2tf(bR[i].y), f2tf(bR[i].z), f2tf(bR[i].w));
            *(uint4*)&Bs[br * BSTR + bc] = u;
        }
        __syncthreads();
    }

    // epilogue
    #pragma unroll
    for (int mi = 0; mi < MI; mi++) {
        #pragma unroll
        for (int ni = 0; ni < NI; ni++) {
            int col = bn + wn * WN + ni * 8 + 2 * (lane & 3);
            #pragma unroll
            for (int h = 0; h < 2; h++) {
                int row = bm + wm * WM + mi * 16 + (lane >> 2) + h * 8;
                float v0 = acc[mi][ni][h * 2 + 0] * alpha;
                float v1 = acc[mi][ni][h * 2 + 1] * alpha;
                if (BIAS) { v0 += bias[col]; v1 += bias[col + 1]; }
                if (RELU) { v0 = fmaxf(v0, 0.f); v1 = fmaxf(v1, 0.f); }
                if (RES) {
                    float2 r2 = *(const float2*)&Rp[(long)row * ldc + col];
                    v0 += r2.x; v1 += r2.y;
                }
                float2 o; o.x = v0; o.y = v1;
                *(float2*)&C[(long)row * ldc + col] = o;
            }
        }
    }
}

// ----------------------------------------------------------------------------
// Host orchestration
// ----------------------------------------------------------------------------
extern "C" void kernel_launch(void* const* d_in, const int* in_sizes, int n_in,
                              void* d_out, int out_size) {
    const float* x     = (const float*)d_in[0];
    const float* enc   = (const float*)d_in[1];
    // d_in[2] = tgt_mask (always causal tril; handled analytically)
    const float* sa_wq = (const float*)d_in[3];
    const float* sa_bq = (const float*)d_in[4];
    const float* sa_wk = (const float*)d_in[5];
    const float* sa_bk = (const float*)d_in[6];
    const float* sa_wv = (const float*)d_in[7];
    const float* sa_bv = (const float*)d_in[8];
    const float* sa_wo = (const float*)d_in[9];
    const float* sa_bo = (const float*)d_in[10];
    const float* ca_wq = (const float*)d_in[11];
    const float* ca_bq = (const float*)d_in[12];
    const float* ca_wk = (const float*)d_in[13];
    const float* ca_bk = (const float*)d_in[14];
    const float* ca_wv = (const float*)d_in[15];
    const float* ca_bv = (const float*)d_in[16];
    const float* ca_wo = (const float*)d_in[17];
    const float* ca_bo = (const float*)d_in[18];
    const float* ff_w1 = (const float*)d_in[19];
    const float* ff_b1 = (const float*)d_in[20];
    const float* ff_w2 = (const float*)d_in[21];
    const float* ff_b2 = (const float*)d_in[22];
    const float* ln1g  = (const float*)d_in[23];
    const float* ln1b  = (const float*)d_in[24];
    const float* ln2g  = (const float*)d_in[25];
    const float* ln2b  = (const float*)d_in[26];
    const float* ln3g  = (const float*)d_in[27];
    const float* ln3b  = (const float*)d_in[28];
    float* out = (float*)d_out;

    float *H, *Q, *K, *V, *A, *X1, *Kt, *F1, *S;
    cudaGetSymbolAddress((void**)&H,  g_H);
    cudaGetSymbolAddress((void**)&Q,  g_Q);
    cudaGetSymbolAddress((void**)&K,  g_K);
    cudaGetSymbolAddress((void**)&V,  g_V);
    cudaGetSymbolAddress((void**)&A,  g_A);
    cudaGetSymbolAddress((void**)&X1, g_X1);
    cudaGetSymbolAddress((void**)&Kt, g_Kt);
    cudaGetSymbolAddress((void**)&F1, g_F1);
    cudaGetSymbolAddress((void**)&S,  g_S);

    const float iscale = 0.125f;   // 1/sqrt(64)
    const long sQb = (long)T_ * ED_;
    const long sQh = HD_;
    const long sKtb = (long)NH_ * HD_ * S_;
    const long sKth = (long)HD_ * S_;
    const long sSb = (long)NH_ * T_ * S_;
    const long sSh = (long)T_ * S_;

    dim3 gProj(ED_ / 128, BT_ / 128, 1);        // (8, 32)
    dim3 gQK(S_ / 128, T_ / 128, B_ * NH_);     // (16, 16, 32)
    dim3 gPV(1, T_ / 128, B_ * NH_);            // (1, 16, 32)
    dim3 gFF1(FF_ / 128, BT_ / 128, 1);         // (32, 32)

    // ---------------- self-attention block ----------------
    ln_k<<<BT_, 256>>>(x, ln1g, ln1b, H);
    mma_gemm<128, 2, 4, true, false, false, false, false><<<gProj, 256>>>(H, sa_wq, sa_bq, nullptr, Q,
        ED_, ED_, ED_, ED_, 0, 0, 0, 0, 0, 0, 1, 1.0f);
    mma_gemm<128, 2, 4, true, false, false, false, false><<<gProj, 256>>>(H, sa_wk, sa_bk, nullptr, K,
        ED_, ED_, ED_, ED_, 0, 0, 0, 0, 0, 0, 1, 1.0f);
    mma_gemm<128, 2, 4, true, false, false, false, false><<<gProj, 256>>>(H, sa_wv, sa_bv, nullptr, V,
        ED_, ED_, ED_, ED_, 0, 0, 0, 0, 0, 0, 1, 1.0f);
    transpose_k<<<(B_ * NH_ * HD_ * S_) / 256, 256>>>(K, Kt);
    mma_gemm<128, 2, 4, false, false, false, true, false><<<gQK, 256>>>(Q, Kt, nullptr, nullptr, S,
        HD_, ED_, S_, S_, sQb, sQh, sKtb, sKth, sSb, sSh, NH_, iscale);
    softmax_k<true><<<dim3(T_, NH_, B_), 256>>>(S);
    mma_gemm<64, 4, 2, false, false, false, false, true><<<gPV, 256>>>(S, V, nullptr, nullptr, A,
        S_, S_, ED_, ED_, sSb, sSh, sQb, sQh, sQb, sQh, NH_, 1.0f);
    mma_gemm<128, 2, 4, true, false, true, false, false><<<gProj, 256>>>(A, sa_wo, sa_bo, x, X1,
        ED_, ED_, ED_, ED_, 0, 0, 0, 0, 0, 0, 1, 1.0f);

    // ---------------- cross-attention block ----------------
    ln_k<<<BT_, 256>>>(X1, ln2g, ln2b, H);
    mma_gemm<128, 2, 4, true, false, false, false, false><<<gProj, 256>>>(H, ca_wq, ca_bq, nullptr, Q,
        ED_, ED_, ED_, ED_, 0, 0, 0, 0, 0, 0, 1, 1.0f);
    mma_gemm<128, 2, 4, true, false, false, false, false><<<gProj, 256>>>(enc, ca_wk, ca_bk, nullptr, K,
        ED_, ED_, ED_, ED_, 0, 0, 0, 0, 0, 0, 1, 1.0f);
    mma_gemm<128, 2, 4, true, false, false, false, false><<<gProj, 256>>>(enc, ca_wv, ca_bv, nullptr, V,
        ED_, ED_, ED_, ED_, 0, 0, 0, 0, 0, 0, 1, 1.0f);
    transpose_k<<<(B_ * NH_ * HD_ * S_) / 256, 256>>>(K, Kt);
    mma_gemm<128, 2, 4, false, false, false, false, false><<<gQK, 256>>>(Q, Kt, nullptr, nullptr, S,
        HD_, ED_, S_, S_, sQb, sQh, sKtb, sKth, sSb, sSh, NH_, iscale);
    softmax_k<false><<<dim3(T_, NH_, B_), 256>>>(S);
    mma_gemm<64, 4, 2, false, false, false, false, false><<<gPV, 256>>>(S, V, nullptr, nullptr, A,
        S_, S_, ED_, ED_, sSb, sSh, sQb, sQh, sQb, sQh, NH_, 1.0f);
    mma_gemm<128, 2, 4, true, false, true, false, false><<<gProj, 256>>>(A, ca_wo, ca_bo, X1, out,
        ED_, ED_, ED_, ED_, 0, 0, 0, 0, 0, 0, 1, 1.0f);

    // ---------------- feed-forward block ----------------
    ln_k<<<BT_, 256>>>(out, ln3g, ln3b, H);
    mma_gemm<128, 2, 4, true, true, false, false, false><<<gFF1, 256>>>(H, ff_w1, ff_b1, nullptr, F1,
        ED_, ED_, FF_, FF_, 0, 0, 0, 0, 0, 0, 1, 1.0f);
    mma_gemm<128, 2, 4, true, false, true, false, false><<<gProj, 256>>>(F1, ff_w2, ff_b2, out, out,
        FF_, FF_, ED_, ED_, 0, 0, 0, 0, 0, 0, 1, 1.0f);
}

// round 10
// speedup vs baseline: 3.3755x; 1.4165x over previous
#include <cuda_runtime.h>
#include <math.h>
#include <stdint.h>

// ----------------------------------------------------------------------------
// Problem constants
// ----------------------------------------------------------------------------
#define B_   2
#define T_   2048
#define S_   2048
#define ED_  1024
#define NH_  16
#define HD_  64
#define FF_  4096
#define BT_  (B_ * T_)          // 4096 rows

// ----------------------------------------------------------------------------
// Device scratch (no allocations allowed -> __device__ globals)
// ----------------------------------------------------------------------------
__device__ float g_H [BT_ * ED_];                 // LN output
__device__ float g_Q [BT_ * ED_];
__device__ float g_K [BT_ * ED_];
__device__ float g_V [BT_ * ED_];
__device__ float g_A [BT_ * ED_];                 // attention output (pre-Wo)
__device__ float g_X1[BT_ * ED_];                 // residual after self-attn
__device__ float g_F1[BT_ * FF_];                 // FFN hidden

// ----------------------------------------------------------------------------
// fp32 -> tf32 (round-to-nearest) helper
// ----------------------------------------------------------------------------
__device__ __forceinline__ uint32_t f2tf(float f) {
    uint32_t u;
    asm("cvt.rna.tf32.f32 %0, %1;" : "=r"(u) : "f"(f));
    return u;
}

// ----------------------------------------------------------------------------
// LayerNorm: one block per row of 1024
// ----------------------------------------------------------------------------
__global__ __launch_bounds__(256) void ln_k(const float* __restrict__ x,
                                            const float* __restrict__ g,
                                            const float* __restrict__ b,
                                            float* __restrict__ o) {
    __shared__ float red[8];
    __shared__ float s_mu, s_rstd;
    long base = (long)blockIdx.x * ED_;
    int t = threadIdx.x;
    float4 v = *(const float4*)(x + base + t * 4);

    float s = v.x + v.y + v.z + v.w;
    #pragma unroll
    for (int off = 16; off; off >>= 1) s += __shfl_xor_sync(0xffffffffu, s, off);
    if ((t & 31) == 0) red[t >> 5] = s;
    __syncthreads();
    if (t == 0) {
        float tot = 0.f;
        #pragma unroll
        for (int i = 0; i < 8; i++) tot += red[i];
        s_mu = tot * (1.0f / ED_);
    }
    __syncthreads();
    float mu = s_mu;
    float dx = v.x - mu, dy = v.y - mu, dz = v.z - mu, dw = v.w - mu;
    float ss = dx * dx + dy * dy + dz * dz + dw * dw;
    #pragma unroll
    for (int off = 16; off; off >>= 1) ss += __shfl_xor_sync(0xffffffffu, ss, off);
    __syncthreads();
    if ((t & 31) == 0) red[t >> 5] = ss;
    __syncthreads();
    if (t == 0) {
        float tot = 0.f;
        #pragma unroll
        for (int i = 0; i < 8; i++) tot += red[i];
        s_rstd = rsqrtf(tot * (1.0f / ED_) + 1e-5f);
    }
    __syncthreads();
    float rstd = s_rstd;
    float4 gv = *(const float4*)(g + t * 4);
    float4 bv = *(const float4*)(b + t * 4);
    float4 ov;
    ov.x = dx * rstd * gv.x + bv.x;
    ov.y = dy * rstd * gv.y + bv.y;
    ov.z = dz * rstd * gv.z + bv.z;
    ov.w = dw * rstd * gv.w + bv.w;
    *(float4*)(o + base + t * 4) = ov;
}

// ----------------------------------------------------------------------------
// Fused flash attention (tf32 mma). One block per (q-tile 128, head, batch).
// 256 threads = 8 warps; warp w owns q rows [w*16, w*16+16).
// Smem: KQ region (Q staging then K tiles, [128][68]), V [128][72], P [128][132].
// K kept [s][d] (no transpose): row.col B-fragment reads Ks[n][k] directly.
// Scale 1/sqrt(64) folded into Q. Causal: diagonal tile masked, loop truncated.
// Output O[b*T+q][h*64+d] (same layout as the old PV output).
// ----------------------------------------------------------------------------
#define QSTR 68
#define VSTR 72
#define PSTR 132
#define FSMEM ((128 * QSTR + 128 * VSTR + 128 * PSTR) * 4)   // 139264 B

template <bool CAUSAL>
__global__ __launch_bounds__(256) void flash_k(
    const float* __restrict__ Qg, const float* __restrict__ Kg,
    const float* __restrict__ Vg, float* __restrict__ Og) {

    extern __shared__ uint32_t sm[];
    uint32_t* KQ = sm;                       // [128][QSTR]
    uint32_t* Vs = sm + 128 * QSTR;          // [128][VSTR]
    uint32_t* Ps = sm + 128 * (QSTR + VSTR); // [128][PSTR]

    int t = threadIdx.x, lane = t & 31, w = t >> 5;
    int j = lane & 3, r4 = lane >> 2;
    int qt = CAUSAL ? (gridDim.x - 1 - blockIdx.x) : blockIdx.x;
    int h  = blockIdx.y, b = blockIdx.z;
    int hoff = h * HD_;
    long qrow0 = (long)b * T_ + qt * 128;
    long krow0 = (long)b * S_;

    // ---- stage Q (scaled) and extract fragments to registers ----
    #pragma unroll
    for (int i = 0; i < 8; i++) {
        int idx = t + i * 256; int row = idx >> 4, c = (idx & 15) * 4;
        float4 q = *(const float4*)&Qg[(qrow0 + row) * ED_ + hoff + c];
        uint32_t* p = &KQ[row * QSTR + c];
        p[0] = f2tf(q.x * 0.125f); p[1] = f2tf(q.y * 0.125f);
        p[2] = f2tf(q.z * 0.125f); p[3] = f2tf(q.w * 0.125f);
    }
    __syncthreads();
    int r0 = w * 16 + r4;
    uint32_t aq[8][4];
    #pragma unroll
    for (int ks = 0; ks < 8; ks++) {
        int k = ks * 8 + j;
        aq[ks][0] = KQ[r0 * QSTR + k];
        aq[ks][1] = KQ[(r0 + 8) * QSTR + k];
        aq[ks][2] = KQ[r0 * QSTR + k + 4];
        aq[ks][3] = KQ[(r0 + 8) * QSTR + k + 4];
    }
    __syncthreads();

    float m[2] = {-1e30f, -1e30f};
    float l[2] = {0.f, 0.f};
    float accO[8][4];
    #pragma unroll
    for (int nv = 0; nv < 8; nv++)
        #pragma unroll
        for (int c = 0; c < 4; c++) accO[nv][c] = 0.f;

    int ktiles = CAUSAL ? (qt + 1) : (S_ / 128);

    for (int kt = 0; kt < ktiles; kt++) {
        int kbase = kt * 128;
        // ---- load K (rows [s][d]) and V tiles ----
        #pragma unroll
        for (int i = 0; i < 8; i++) {
            int idx = t + i * 256; int row = idx >> 4, c = (idx & 15) * 4;
            long grow = (krow0 + kbase + row) * ED_ + hoff + c;
            float4 kv = *(const float4*)&Kg[grow];
            float4 vv = *(const float4*)&Vg[grow];
            uint32_t* pk = &KQ[row * QSTR + c];
            pk[0] = f2tf(kv.x); pk[1] = f2tf(kv.y);
            pk[2] = f2tf(kv.z); pk[3] = f2tf(kv.w);
            uint32_t* pv = &Vs[row * VSTR + c];
            pv[0] = f2tf(vv.x); pv[1] = f2tf(vv.y);
            pv[2] = f2tf(vv.z); pv[3] = f2tf(vv.w);
        }
        __syncthreads();

        // ---- S = Q @ K^T ----
        float accS[16][4];
        #pragma unroll
        for (int ni = 0; ni < 16; ni++)
            #pragma unroll
            for (int c = 0; c < 4; c++) accS[ni][c] = 0.f;

        #pragma unroll
        for (int ks = 0; ks < 8; ks++) {
            int kk = ks * 8 + j;
            #pragma unroll
            for (int ni = 0; ni < 16; ni++) {
                int n = ni * 8 + r4;
                uint32_t b0 = KQ[n * QSTR + kk];
                uint32_t b1 = KQ[n * QSTR + kk + 4];
                asm volatile(
                    "mma.sync.aligned.m16n8k8.row.col.f32.tf32.tf32.f32 "
                    "{%0,%1,%2,%3},{%4,%5,%6,%7},{%8,%9},{%0,%1,%2,%3};"
                    : "+f"(accS[ni][0]), "+f"(accS[ni][1]),
                      "+f"(accS[ni][2]), "+f"(accS[ni][3])
                    : "r"(aq[ks][0]), "r"(aq[ks][1]), "r"(aq[ks][2]), "r"(aq[ks][3]),
                      "r"(b0), "r"(b1));
            }
        }

        // ---- causal mask on the diagonal tile ----
        if (CAUSAL && kt == qt) {
            int rl0 = w * 16 + r4;
            #pragma unroll
            for (int ni = 0; ni < 16; ni++) {
                int n0 = ni * 8 + 2 * j;
                if (n0 + 0 > rl0)     accS[ni][0] = -1e30f;
                if (n0 + 1 > rl0)     accS[ni][1] = -1e30f;
                if (n0 + 0 > rl0 + 8) accS[ni][2] = -1e30f;
                if (n0 + 1 > rl0 + 8) accS[ni][3] = -1e30f;
            }
        }

        // ---- online softmax update ----
        #pragma unroll
        for (int hh = 0; hh < 2; hh++) {
            float mx = -1e30f;
            #pragma unroll
            for (int ni = 0; ni < 16; ni++)
                mx = fmaxf(mx, fmaxf(accS[ni][2 * hh], accS[ni][2 * hh + 1]));
            mx = fmaxf(mx, __shfl_xor_sync(0xffffffffu, mx, 1));
            mx = fmaxf(mx, __shfl_xor_sync(0xffffffffu, mx, 2));
            float mnew = fmaxf(m[hh], mx);
            float fac = __expf(m[hh] - mnew);
            float sum = 0.f;
            #pragma unroll
            for (int ni = 0; ni < 16; ni++) {
                float p0 = __expf(accS[ni][2 * hh] - mnew);
                float p1 = __expf(accS[ni][2 * hh + 1] - mnew);
                accS[ni][2 * hh] = p0; accS[ni][2 * hh + 1] = p1;
                sum += p0 + p1;
            }
            sum += __shfl_xor_sync(0xffffffffu, sum, 1);
            sum += __shfl_xor_sync(0xffffffffu, sum, 2);
            l[hh] = l[hh] * fac + sum;
            m[hh] = mnew;
            #pragma unroll
            for (int nv = 0; nv < 8; nv++) {
                accO[nv][2 * hh]     *= fac;
                accO[nv][2 * hh + 1] *= fac;
            }
        }

        // ---- store P (per-warp region) as tf32 ----
        #pragma unroll
        for (int ni = 0; ni < 16; ni++) {
            int off = ni * 8 + 2 * j;
            uint2 u0 = make_uint2(f2tf(accS[ni][0]), f2tf(accS[ni][1]));
            uint2 u1 = make_uint2(f2tf(accS[ni][2]), f2tf(accS[ni][3]));
            *(uint2*)&Ps[r0 * PSTR + off] = u0;
            *(uint2*)&Ps[(r0 + 8) * PSTR + off] = u1;
        }
        __syncwarp();

        // ---- O += P @ V ----
        #pragma unroll
        for (int ks = 0; ks < 16; ks++) {
            int kk = ks * 8 + j;
            uint32_t a0 = Ps[r0 * PSTR + kk];
            uint32_t a1 = Ps[(r0 + 8) * PSTR + kk];
            uint32_t a2 = Ps[r0 * PSTR + kk + 4];
            uint32_t a3 = Ps[(r0 + 8) * PSTR + kk + 4];
            #pragma unroll
            for (int nv = 0; nv < 8; nv++) {
                int n = nv * 8 + r4;
                uint32_t b0 = Vs[kk * VSTR + n];
                uint32_t b1 = Vs[(kk + 4) * VSTR + n];
                asm volatile(
                    "mma.sync.aligned.m16n8k8.row.col.f32.tf32.tf32.f32 "
                    "{%0,%1,%2,%3},{%4,%5,%6,%7},{%8,%9},{%0,%1,%2,%3};"
                    : "+f"(accO[nv][0]), "+f"(accO[nv][1]),
                      "+f"(accO[nv][2]), "+f"(accO[nv][3])
                    : "r"(a0), "r"(a1), "r"(a2), "r"(a3),
                      "r"(b0), "r"(b1));
            }
        }
        __syncthreads();     // all warps done with K/V before next tile load
    }

    // ---- epilogue: normalize and write O ----
    float inv0 = 1.0f / l[0], inv1 = 1.0f / l[1];
    #pragma unroll
    for (int nv = 0; nv < 8; nv++) {
        int col = hoff + nv * 8 + 2 * j;
        long row = qrow0 + w * 16 + r4;
        float2 o0; o0.x = accO[nv][0] * inv0; o0.y = accO[nv][1] * inv0;
        float2 o1; o1.x = accO[nv][2] * inv1; o1.y = accO[nv][3] * inv1;
        *(float2*)&Og[row * ED_ + col] = o0;
        *(float2*)&Og[(row + 8) * ED_ + col] = o1;
    }
}

// ----------------------------------------------------------------------------
// tf32 tensor-core GEMM: C[M,N] = alpha*(A[M,K]@B[K,N]) (+bias)(relu)(+R)
// BM=128, BK=32, 256 threads (8 warps as WARPS_M x WARPS_N).
// ----------------------------------------------------------------------------
template <int BN, int WARPS_M, int WARPS_N, bool BIAS, bool RELU, bool RES>
__global__ __launch_bounds__(256) void mma_gemm(
    const float* __restrict__ A, const float* __restrict__ Bm,
    const float* __restrict__ bias, const float* __restrict__ R,
    float* __restrict__ C,
    int K, int lda, int ldb, int ldc, float alpha) {

    constexpr int BM = 128, BK = 32;
    constexpr int WM = BM / WARPS_M, WN = BN / WARPS_N;
    constexpr int MI = WM / 16, NI = WN / 8;
    constexpr int ASTR = BK + 4;
    constexpr int BSTR = BN + 8;
    constexpr int NLA = (BM * BK) / (4 * 256);
    constexpr int NLB = (BK * BN) / (4 * 256);

    int bm = blockIdx.y * BM;
    int bn = blockIdx.x * BN;

    __shared__ uint32_t As[BM * ASTR];
    __shared__ uint32_t Bs[BK * BSTR];

    int t = threadIdx.x, lane = t & 31, warp = t >> 5;
    int wm = warp / WARPS_N, wn = warp % WARPS_N;

    float4 aR[NLA], bR[NLB];

    #pragma unroll
    for (int i = 0; i < NLA; i++) {
        int jj = t + i * 256; int ar = jj >> 3, ac = (jj & 7) * 4;
        aR[i] = *(const float4*)&A[(long)(bm + ar) * lda + ac];
    }
    #pragma unroll
    for (int i = 0; i < NLB; i++) {
        int jj = t + i * 256;
        int br = (BN == 128) ? (jj >> 5) : (jj >> 4);
        int bc = ((BN == 128) ? (jj & 31) : (jj & 15)) * 4;
        bR[i] = *(const float4*)&Bm[(long)br * ldb + bn + bc];
    }
    #pragma unroll
    for (int i = 0; i < NLA; i++) {
        int jj = t + i * 256; int ar = jj >> 3, ac = (jj & 7) * 4;
        uint4 u = make_uint4(f2tf(aR[i].x), f2tf(aR[i].y), f2tf(aR[i].z), f2tf(aR[i].w));
        *(uint4*)&As[ar * ASTR + ac] = u;
    }
    #pragma unroll
    for (int i = 0; i < NLB; i++) {
        int jj = t + i * 256;
        int br = (BN == 128) ? (jj >> 5) : (jj >> 4);
        int bc = ((BN == 128) ? (jj & 31) : (jj & 15)) * 4;
        uint4 u = make_uint4(f2tf(bR[i].x), f2tf(bR[i].y), f2tf(bR[i].z), f2tf(bR[i].w));
        *(uint4*)&Bs[br * BSTR + bc] = u;
    }
    __syncthreads();

    float acc[MI][NI][4];
    #pragma unroll
    for (int mi = 0; mi < MI; mi++)
        #pragma unroll
        for (int ni = 0; ni < NI; ni++)
            #pragma unroll
            for (int c = 0; c < 4; c++) acc[mi][ni][c] = 0.f;

    for (int kt = BK;; kt += BK) {
        bool more = kt < K;
        if (more) {
            #pragma unroll
            for (int i = 0; i < NLA; i++) {
                int jj = t + i * 256; int ar = jj >> 3, ac = (jj & 7) * 4;
                aR[i] = *(const float4*)&A[(long)(bm + ar) * lda + kt + ac];
            }
            #pragma unroll
            for (int i = 0; i < NLB; i++) {
                int jj = t + i * 256;
                int br = (BN == 128) ? (jj >> 5) : (jj >> 4);
                int bc = ((BN == 128) ? (jj & 31) : (jj & 15)) * 4;
                bR[i] = *(const float4*)&Bm[(long)(kt + br) * ldb + bn + bc];
            }
        }

        #pragma unroll
        for (int ks = 0; ks < 4; ks++) {
            int k0 = ks * 8;
            uint32_t af[MI][4], bf[NI][2];
            #pragma unroll
            for (int mi = 0; mi < MI; mi++) {
                int rr = wm * WM + mi * 16 + (lane >> 2);
                int kk = k0 + (lane & 3);
                af[mi][0] = As[rr * ASTR + kk];
                af[mi][1] = As[(rr + 8) * ASTR + kk];
                af[mi][2] = As[rr * ASTR + kk + 4];
                af[mi][3] = As[(rr + 8) * ASTR + kk + 4];
            }
            #pragma unroll
            for (int ni = 0; ni < NI; ni++) {
                int c0 = wn * WN + ni * 8 + (lane >> 2);
                int kk = k0 + (lane & 3);
                bf[ni][0] = Bs[kk * BSTR + c0];
                bf[ni][1] = Bs[(kk + 4) * BSTR + c0];
            }
            #pragma unroll
            for (int mi = 0; mi < MI; mi++)
                #pragma unroll
                for (int ni = 0; ni < NI; ni++)
                    asm volatile(
                        "mma.sync.aligned.m16n8k8.row.col.f32.tf32.tf32.f32 "
                        "{%0,%1,%2,%3},{%4,%5,%6,%7},{%8,%9},{%0,%1,%2,%3};"
                        : "+f"(acc[mi][ni][0]), "+f"(acc[mi][ni][1]),
                          "+f"(acc[mi][ni][2]), "+f"(acc[mi][ni][3])
                        : "r"(af[mi][0]), "r"(af[mi][1]), "r"(af[mi][2]), "r"(af[mi][3]),
                          "r"(bf[ni][0]), "r"(bf[ni][1]));
        }
        if (!more) break;
        __syncthreads();
        #pragma unroll
        for (int i = 0; i < NLA; i++) {
            int jj = t + i * 256; int ar = jj >> 3, ac = (jj & 7) * 4;
            uint4 u = make_uint4(f2tf(aR[i].x), f2tf(aR[i].y), f2tf(aR[i].z), f2tf(aR[i].w));
            *(uint4*)&As[ar * ASTR + ac] = u;
        }
        #pragma unroll
        for (int i = 0; i < NLB; i++) {
            int jj = t + i * 256;
            int br = (BN == 128) ? (jj >> 5) : (jj >> 4);
            int bc = ((BN == 128) ? (jj & 31) : (jj & 15)) * 4;
            uint4 u = make_uint4(f2tf(bR[i].x), f2tf(bR[i].y), f2tf(bR[i].z), f2tf(bR[i].w));
            *(uint4*)&Bs[br * BSTR + bc] = u;
        }
        __syncthreads();
    }

    #pragma unroll
    for (int mi = 0; mi < MI; mi++) {
        #pragma unroll
        for (int ni = 0; ni < NI; ni++) {
            int col = bn + wn * WN + ni * 8 + 2 * (lane & 3);
            #pragma unroll
            for (int hh = 0; hh < 2; hh++) {
                int row = bm + wm * WM + mi * 16 + (lane >> 2) + hh * 8;
                float v0 = acc[mi][ni][hh * 2 + 0] * alpha;
                float v1 = acc[mi][ni][hh * 2 + 1] * alpha;
                if (BIAS) { v0 += bias[col]; v1 += bias[col + 1]; }
                if (RELU) { v0 = fmaxf(v0, 0.f); v1 = fmaxf(v1, 0.f); }
                if (RES) {
                    float2 r2 = *(const float2*)&R[(long)row * ldc + col];
                    v0 += r2.x; v1 += r2.y;
                }
                float2 o; o.x = v0; o.y = v1;
                *(float2*)&C[(long)row * ldc + col] = o;
            }
        }
    }
}

// ----------------------------------------------------------------------------
// Host orchestration
// ----------------------------------------------------------------------------
extern "C" void kernel_launch(void* const* d_in, const int* in_sizes, int n_in,
                              void* d_out, int out_size) {
    const float* x     = (const float*)d_in[0];
    const float* enc   = (const float*)d_in[1];
    // d_in[2] = tgt_mask (always causal tril; handled analytically)
    const float* sa_wq = (const float*)d_in[3];
    const float* sa_bq = (const float*)d_in[4];
    const float* sa_wk = (const float*)d_in[5];
    const float* sa_bk = (const float*)d_in[6];
    const float* sa_wv = (const float*)d_in[7];
    const float* sa_bv = (const float*)d_in[8];
    const float* sa_wo = (const float*)d_in[9];
    const float* sa_bo = (const float*)d_in[10];
    const float* ca_wq = (const float*)d_in[11];
    const float* ca_bq = (const float*)d_in[12];
    const float* ca_wk = (const float*)d_in[13];
    const float* ca_bk = (const float*)d_in[14];
    const float* ca_wv = (const float*)d_in[15];
    const float* ca_bv = (const float*)d_in[16];
    const float* ca_wo = (const float*)d_in[17];
    const float* ca_bo = (const float*)d_in[18];
    const float* ff_w1 = (const float*)d_in[19];
    const float* ff_b1 = (const float*)d_in[20];
    const float* ff_w2 = (const float*)d_in[21];
    const float* ff_b2 = (const float*)d_in[22];
    const float* ln1g  = (const float*)d_in[23];
    const float* ln1b  = (const float*)d_in[24];
    const float* ln2g  = (const float*)d_in[25];
    const float* ln2b  = (const float*)d_in[26];
    const float* ln3g  = (const float*)d_in[27];
    const float* ln3b  = (const float*)d_in[28];
    float* out = (float*)d_out;

    float *H, *Q, *K, *V, *A, *X1, *F1;
    cudaGetSymbolAddress((void**)&H,  g_H);
    cudaGetSymbolAddress((void**)&Q,  g_Q);
    cudaGetSymbolAddress((void**)&K,  g_K);
    cudaGetSymbolAddress((void**)&V,  g_V);
    cudaGetSymbolAddress((void**)&A,  g_A);
    cudaGetSymbolAddress((void**)&X1, g_X1);
    cudaGetSymbolAddress((void**)&F1, g_F1);

    static bool attr_done = false;
    if (!attr_done) {
        cudaFuncSetAttribute(flash_k<true>,
            cudaFuncAttributeMaxDynamicSharedMemorySize, FSMEM);
        cudaFuncSetAttribute(flash_k<false>,
            cudaFuncAttributeMaxDynamicSharedMemorySize, FSMEM);
        attr_done = true;
    }

    dim3 gProj(ED_ / 128, BT_ / 128, 1);        // (8, 32)
    dim3 gFF1(FF_ / 128, BT_ / 128, 1);         // (32, 32)
    dim3 gFlash(T_ / 128, NH_, B_);             // (16, 16, 2)

    // ---------------- self-attention block ----------------
    ln_k<<<BT_, 256>>>(x, ln1g, ln1b, H);
    mma_gemm<128, 2, 4, true, false, false><<<gProj, 256>>>(H, sa_wq, sa_bq, nullptr, Q,
        ED_, ED_, ED_, ED_, 1.0f);
    mma_gemm<128, 2, 4, true, false, false><<<gProj, 256>>>(H, sa_wk, sa_bk, nullptr, K,
        ED_, ED_, ED_, ED_, 1.0f);
    mma_gemm<128, 2, 4, true, false, false><<<gProj, 256>>>(H, sa_wv, sa_bv, nullptr, V,
        ED_, ED_, ED_, ED_, 1.0f);
    flash_k<true><<<gFlash, 256, FSMEM>>>(Q, K, V, A);
    mma_gemm<128, 2, 4, true, false, true><<<gProj, 256>>>(A, sa_wo, sa_bo, x, X1,
        ED_, ED_, ED_, ED_, 1.0f);

    // ---------------- cross-attention block ----------------
    ln_k<<<BT_, 256>>>(X1, ln2g, ln2b, H);
    mma_gemm<128, 2, 4, true, false, false><<<gProj, 256>>>(H, ca_wq, ca_bq, nullptr, Q,
        ED_, ED_, ED_, ED_, 1.0f);
    mma_gemm<128, 2, 4, true, false, false><<<gProj, 256>>>(enc, ca_wk, ca_bk, nullptr, K,
        ED_, ED_, ED_, ED_, 1.0f);
    mma_gemm<128, 2, 4, true, false, false><<<gProj, 256>>>(enc, ca_wv, ca_bv, nullptr, V,
        ED_, ED_, ED_, ED_, 1.0f);
    flash_k<false><<<gFlash, 256, FSMEM>>>(Q, K, V, A);
    mma_gemm<128, 2, 4, true, false, true><<<gProj, 256>>>(A, ca_wo, ca_bo, X1, out,
        ED_, ED_, ED_, ED_, 1.0f);

    // ---------------- feed-forward block ----------------
    ln_k<<<BT_, 256>>>(out, ln3g, ln3b, H);
    mma_gemm<128, 2, 4, true, true, false><<<gFF1, 256>>>(H, ff_w1, ff_b1, nullptr, F1,
        ED_, ED_, FF_, FF_, 1.0f);
    mma_gemm<128, 2, 4, true, false, true><<<gProj, 256>>>(F1, ff_w2, ff_b2, out, out,
        FF_, FF_, ED_, ED_, 1.0f);
}

// round 16
// speedup vs baseline: 6.1164x; 1.8120x over previous
#include <cuda_runtime.h>
#include <cuda_fp16.h>
#include <math.h>
#include <stdint.h>

// ----------------------------------------------------------------------------
// Problem constants
// ----------------------------------------------------------------------------
#define B_   2
#define T_   2048
#define S_   2048
#define ED_  1024
#define NH_  16
#define HD_  64
#define FF_  4096
#define BT_  (B_ * T_)          // 4096 rows

// ----------------------------------------------------------------------------
// Device scratch (no allocations allowed -> __device__ globals)
// ----------------------------------------------------------------------------
__device__ __half g_Hh  [BT_ * ED_];     // LN output (fp16)
__device__ __half g_Qh  [BT_ * ED_];
__device__ __half g_Kh  [BT_ * ED_];
__device__ __half g_Vh  [BT_ * ED_];
__device__ __half g_Ah  [BT_ * ED_];     // attention output (fp16)
__device__ __half g_F1h [BT_ * FF_];     // FFN hidden (fp16)
__device__ __half g_encH[BT_ * ED_];     // encoder outputs (fp16)
__device__ __half g_W16 [ED_ * FF_];     // converted weight scratch
__device__ float  g_X1  [BT_ * ED_];     // residual after self-attn (fp32)

// ----------------------------------------------------------------------------
// Helpers
// ----------------------------------------------------------------------------
__device__ __forceinline__ uint32_t smem_u32(const void* p) {
    uint32_t a;
    asm("{ .reg .u64 t; cvta.to.shared.u64 t, %1; cvt.u32.u64 %0, t; }"
        : "=r"(a) : "l"(p));
    return a;
}

__device__ __forceinline__ uint32_t pack2h(float lo, float hi) {
    __half2 h = __floats2half2_rn(lo, hi);
    return *reinterpret_cast<uint32_t*>(&h);
}

#define CP_ASYNC16(dst, src) \
    asm volatile("cp.async.cg.shared.global [%0], [%1], 16;" \
                 :: "r"(dst), "l"(src) : "memory")
#define CP_COMMIT() asm volatile("cp.async.commit_group;" ::: "memory")
#define CP_WAIT0()  asm volatile("cp.async.wait_group 0;" ::: "memory")
#define CP_WAIT1()  asm volatile("cp.async.wait_group 1;" ::: "memory")

#define LDSM4(r, a) \
    asm volatile("ldmatrix.sync.aligned.m8n8.x4.shared.b16 {%0,%1,%2,%3}, [%4];" \
        : "=r"((r)[0]), "=r"((r)[1]), "=r"((r)[2]), "=r"((r)[3]) : "r"(a))
#define LDSM4T(r, a) \
    asm volatile("ldmatrix.sync.aligned.m8n8.x4.trans.shared.b16 {%0,%1,%2,%3}, [%4];" \
        : "=r"((r)[0]), "=r"((r)[1]), "=r"((r)[2]), "=r"((r)[3]) : "r"(a))

#define HMMA(c, a, b0, b1) \
    asm volatile("mma.sync.aligned.m16n8k16.row.col.f32.f16.f16.f32 " \
        "{%0,%1,%2,%3},{%4,%5,%6,%7},{%8,%9},{%0,%1,%2,%3};" \
        : "+f"((c)[0]), "+f"((c)[1]), "+f"((c)[2]), "+f"((c)[3]) \
        : "r"((a)[0]), "r"((a)[1]), "r"((a)[2]), "r"((a)[3]), "r"(b0), "r"(b1))

// ----------------------------------------------------------------------------
// fp32 -> fp16 conversion (weights / encoder), 8 elems per thread
// ----------------------------------------------------------------------------
__global__ __launch_bounds__(256) void f2h_k(const float* __restrict__ in,
                                             __half* __restrict__ out) {
    long i = ((long)blockIdx.x * 256 + threadIdx.x) * 8;
    float4 a = *(const float4*)(in + i);
    float4 b = *(const float4*)(in + i + 4);
    uint4 u;
    u.x = pack2h(a.x, a.y); u.y = pack2h(a.z, a.w);
    u.z = pack2h(b.x, b.y); u.w = pack2h(b.z, b.w);
    *(uint4*)(out + i) = u;
}

// ----------------------------------------------------------------------------
// LayerNorm: one block per row of 1024, fp32 in -> fp16 out
// ----------------------------------------------------------------------------
__global__ __launch_bounds__(256) void ln_k(const float* __restrict__ x,
                                            const float* __restrict__ g,
                                            const float* __restrict__ b,
                                            __half* __restrict__ o) {
    __shared__ float red[8];
    __shared__ float s_mu, s_rstd;
    long base = (long)blockIdx.x * ED_;
    int t = threadIdx.x;
    float4 v = *(const float4*)(x + base + t * 4);

    float s = v.x + v.y + v.z + v.w;
    #pragma unroll
    for (int off = 16; off; off >>= 1) s += __shfl_xor_sync(0xffffffffu, s, off);
    if ((t & 31) == 0) red[t >> 5] = s;
    __syncthreads();
    if (t == 0) {
        float tot = 0.f;
        #pragma unroll
        for (int i = 0; i < 8; i++) tot += red[i];
        s_mu = tot * (1.0f / ED_);
    }
    __syncthreads();
    float mu = s_mu;
    float dx = v.x - mu, dy = v.y - mu, dz = v.z - mu, dw = v.w - mu;
    float ss = dx * dx + dy * dy + dz * dz + dw * dw;
    #pragma unroll
    for (int off = 16; off; off >>= 1) ss += __shfl_xor_sync(0xffffffffu, ss, off);
    __syncthreads();
    if ((t & 31) == 0) red[t >> 5] = ss;
    __syncthreads();
    if (t == 0) {
        float tot = 0.f;
        #pragma unroll
        for (int i = 0; i < 8; i++) tot += red[i];
        s_rstd = rsqrtf(tot * (1.0f / ED_) + 1e-5f);
    }
    __syncthreads();
    float rstd = s_rstd;
    float4 gv = *(const float4*)(g + t * 4);
    float4 bv = *(const float4*)(b + t * 4);
    float ox = dx * rstd * gv.x + bv.x;
    float oy = dy * rstd * gv.y + bv.y;
    float oz = dz * rstd * gv.z + bv.z;
    float ow = dw * rstd * gv.w + bv.w;
    uint2 u;
    u.x = pack2h(ox, oy); u.y = pack2h(oz, ow);
    *(uint2*)(o + base + t * 4) = u;
}

// ----------------------------------------------------------------------------
// fp16 tensor-core GEMM: C[M,N] = (A[M,K] @ Bw[K,N] + bias) * alpha
//                         (relu) (+R fp32) -> fp32 or fp16 out
// BM=128, BN=128, BK=32, 256 threads (8 warps 2x4), warp tile 64x32.
// cp.async double-buffered; ldmatrix fragment loads; fp32 accumulate.
// ----------------------------------------------------------------------------
template <bool RELU, bool RES, bool OUTH>
__global__ __launch_bounds__(256) void hgemm(
    const __half* __restrict__ A,    // [M, K]
    const __half* __restrict__ Bw,   // [K, N]
    const float* __restrict__ bias,  // [N]
    const float* __restrict__ R,     // [M, N] fp32 residual
    float* __restrict__ Cf,          // fp32 out (if !OUTH)
    __half* __restrict__ Ch,         // fp16 out (if OUTH)
    int K, int N, float alpha) {

    __shared__ __half As[2][128][40];    // 20480 B
    __shared__ __half Bs[2][32][136];    // 17408 B

    int t = threadIdx.x, lane = t & 31, w = t >> 5;
    int wm = w >> 2, wn = w & 3;
    int bm = blockIdx.y * 128, bn = blockIdx.x * 128;

    auto load_tile = [&](int buf, int kt) {
        #pragma unroll
        for (int i = 0; i < 2; i++) {
            int c = t + i * 256;
            int row = c >> 2, ch = c & 3;
            CP_ASYNC16(smem_u32(&As[buf][row][ch * 8]),
                       A + (long)(bm + row) * K + kt + ch * 8);
        }
        #pragma unroll
        for (int i = 0; i < 2; i++) {
            int c = t + i * 256;
            int row = c >> 4, ch = c & 15;
            CP_ASYNC16(smem_u32(&Bs[buf][row][ch * 8]),
                       Bw + (long)(kt + row) * N + bn + ch * 8);
        }
        CP_COMMIT();
    };

    float acc[4][4][4];
    #pragma unroll
    for (int mi = 0; mi < 4; mi++)
        #pragma unroll
        for (int ni = 0; ni < 4; ni++)
            #pragma unroll
            for (int c = 0; c < 4; c++) acc[mi][ni][c] = 0.f;

    int nt = K / 32;
    load_tile(0, 0);

    for (int i = 0; i < nt; i++) {
        if (i + 1 < nt) { load_tile((i + 1) & 1, (i + 1) * 32); CP_WAIT1(); }
        else            { CP_WAIT0(); }
        __syncthreads();
        int buf = i & 1;
        #pragma unroll
        for (int ks = 0; ks < 2; ks++) {
            uint32_t a[4][4];
            #pragma unroll
            for (int mi = 0; mi < 4; mi++)
                LDSM4(a[mi], smem_u32(&As[buf][wm * 64 + mi * 16 + (lane & 15)]
                                          [ks * 16 + (lane >> 4) * 8]));
            #pragma unroll
            for (int nj = 0; nj < 2; nj++) {
                uint32_t bt[4];
                LDSM4T(bt, smem_u32(&Bs[buf][ks * 16 + (lane & 15)]
                                        [wn * 32 + nj * 16 + (lane >> 4) * 8]));
                #pragma unroll
                for (int mi = 0; mi < 4; mi++) {
                    HMMA(acc[mi][nj * 2 + 0], a[mi], bt[0], bt[1]);
                    HMMA(acc[mi][nj * 2 + 1], a[mi], bt[2], bt[3]);
                }
            }
        }
        __syncthreads();
    }

    // ---- epilogue ----
    #pragma unroll
    for (int mi = 0; mi < 4; mi++) {
        #pragma unroll
        for (int ni = 0; ni < 4; ni++) {
            int col = bn + wn * 32 + ni * 8 + (lane & 3) * 2;
            float b0 = bias[col], b1 = bias[col + 1];
            #pragma unroll
            for (int hh = 0; hh < 2; hh++) {
                int row = bm + wm * 64 + mi * 16 + (lane >> 2) + hh * 8;
                float v0 = (acc[mi][ni][hh * 2 + 0] + b0) * alpha;
                float v1 = (acc[mi][ni][hh * 2 + 1] + b1) * alpha;
                if (RELU) { v0 = fmaxf(v0, 0.f); v1 = fmaxf(v1, 0.f); }
                if (RES) {
                    float2 r2 = *(const float2*)&R[(long)row * N + col];
                    v0 += r2.x; v1 += r2.y;
                }
                if (OUTH) {
                    *(uint32_t*)&Ch[(long)row * N + col] = pack2h(v0, v1);
                } else {
                    float2 o; o.x = v0; o.y = v1;
                    *(float2*)&Cf[(long)row * N + col] = o;
                }
            }
        }
    }
}

// ----------------------------------------------------------------------------
// Fused flash attention, fp16 mma. One block per (q-tile 128, head, batch).
// 256 threads = 8 warps; warp w owns q rows [w*16, w*16+16).
// Q pre-scaled by 1/sqrt(64) in projection epilogue.
// P fragments built directly from S accumulator registers (no smem round-trip).
// ----------------------------------------------------------------------------
template <bool CAUSAL>
__global__ __launch_bounds__(256) void hflash(
    const __half* __restrict__ Qg, const __half* __restrict__ Kg,
    const __half* __restrict__ Vg, __half* __restrict__ Og) {

    __shared__ __half KQ[128][72];   // Q staging, then K tiles
    __shared__ __half Vs[128][72];

    int t = threadIdx.x, lane = t & 31, w = t >> 5;
    int j = lane & 3, r4 = lane >> 2;
    int qt = CAUSAL ? (gridDim.x - 1 - blockIdx.x) : blockIdx.x;
    int h = blockIdx.y, b = blockIdx.z;
    int hoff = h * HD_;
    long qrow0 = (long)b * T_ + qt * 128;
    long krow0 = (long)b * S_;

    // ---- stage Q, extract A-fragments to registers ----
    #pragma unroll
    for (int i = 0; i < 4; i++) {
        int c = t + i * 256; int row = c >> 3, ch = c & 7;
        CP_ASYNC16(smem_u32(&KQ[row][ch * 8]),
                   Qg + (qrow0 + row) * ED_ + hoff + ch * 8);
    }
    CP_COMMIT(); CP_WAIT0();
    __syncthreads();
    uint32_t aq[4][4];
    #pragma unroll
    for (int ks = 0; ks < 4; ks++)
        LDSM4(aq[ks], smem_u32(&KQ[w * 16 + (lane & 15)]
                                  [ks * 16 + (lane >> 4) * 8]));
    __syncthreads();

    float m[2] = {-1e30f, -1e30f};
    float l[2] = {0.f, 0.f};
    float accO[8][4];
    #pragma unroll
    for (int nv = 0; nv < 8; nv++)
        #pragma unroll
        for (int c = 0; c < 4; c++) accO[nv][c] = 0.f;

    int ktiles = CAUSAL ? (qt + 1) : (S_ / 128);

    for (int kt = 0; kt < ktiles; kt++) {
        long kb = krow0 + kt * 128;
        #pragma unroll
        for (int i = 0; i < 4; i++) {
            int c = t + i * 256; int row = c >> 3, ch = c & 7;
            long go = (kb + row) * ED_ + hoff + ch * 8;
            CP_ASYNC16(smem_u32(&KQ[row][ch * 8]), Kg + go);
            CP_ASYNC16(smem_u32(&Vs[row][ch * 8]), Vg + go);
        }
        CP_COMMIT(); CP_WAIT0();
        __syncthreads();

        // ---- S = Q @ K^T (K rows are keys: B frag non-trans) ----
        float accS[16][4];
        #pragma unroll
        for (int ni = 0; ni < 16; ni++)
            #pragma unroll
            for (int c = 0; c < 4; c++) accS[ni][c] = 0.f;

        #pragma unroll
        for (int ks = 0; ks < 4; ks++) {
            #pragma unroll
            for (int g = 0; g < 8; g++) {
                uint32_t bk[4];
                LDSM4(bk, smem_u32(&KQ[g * 16 + (lane & 7) + ((lane >> 4) & 1) * 8]
                                      [ks * 16 + ((lane >> 3) & 1) * 8]));
                HMMA(accS[g * 2 + 0], aq[ks], bk[0], bk[1]);
                HMMA(accS[g * 2 + 1], aq[ks], bk[2], bk[3]);
            }
        }

        // ---- causal mask on diagonal tile ----
        if (CAUSAL && kt == qt) {
            int rl0 = w * 16 + r4;
            #pragma unroll
            for (int ni = 0; ni < 16; ni++) {
                int n0 = ni * 8 + 2 * j;
                if (n0 + 0 > rl0)     accS[ni][0] = -1e30f;
                if (n0 + 1 > rl0)     accS[ni][1] = -1e30f;
                if (n0 + 0 > rl0 + 8) accS[ni][2] = -1e30f;
                if (n0 + 1 > rl0 + 8) accS[ni][3] = -1e30f;
            }
        }

        // ---- online softmax ----
        #pragma unroll
        for (int hh = 0; hh < 2; hh++) {
            float mx = -1e30f;
            #pragma unroll
            for (int ni = 0; ni < 16; ni++)
                mx = fmaxf(mx, fmaxf(accS[ni][2 * hh], accS[ni][2 * hh + 1]));
            mx = fmaxf(mx, __shfl_xor_sync(0xffffffffu, mx, 1));
            mx = fmaxf(mx, __shfl_xor_sync(0xffffffffu, mx, 2));
            float mnew = fmaxf(m[hh], mx);
            float fac = __expf(m[hh] - mnew);
            float sum = 0.f;
            #pragma unroll
            for (int ni = 0; ni < 16; ni++) {
                float p0 = __expf(accS[ni][2 * hh] - mnew);
                float p1 = __expf(accS[ni][2 * hh + 1] - mnew);
                accS[ni][2 * hh] = p0; accS[ni][2 * hh + 1] = p1;
                sum += p0 + p1;
            }
            sum += __shfl_xor_sync(0xffffffffu, sum, 1);
            sum += __shfl_xor_sync(0xffffffffu, sum, 2);
            l[hh] = l[hh] * fac + sum;
            m[hh] = mnew;
            #pragma unroll
            for (int nv = 0; nv < 8; nv++) {
                accO[nv][2 * hh]     *= fac;
                accO[nv][2 * hh + 1] *= fac;
            }
        }

        // ---- O += P @ V ; P A-frags built straight from accS registers ----
        #pragma unroll
        for (int kp = 0; kp < 8; kp++) {
            uint32_t pa[4];
            pa[0] = pack2h(accS[2 * kp][0],     accS[2 * kp][1]);
            pa[1] = pack2h(accS[2 * kp][2],     accS[2 * kp][3]);
            pa[2] = pack2h(accS[2 * kp + 1][0], accS[2 * kp + 1][1]);
            pa[3] = pack2h(accS[2 * kp + 1][2], accS[2 * kp + 1][3]);
            #pragma unroll
            for (int dj = 0; dj < 4; dj++) {
                uint32_t bv[4];
                LDSM4T(bv, smem_u32(&Vs[kp * 16 + (lane & 15)]
                                       [dj * 16 + (lane >> 4) * 8]));
                HMMA(accO[dj * 2 + 0], pa, bv[0], bv[1]);
                HMMA(accO[dj * 2 + 1], pa, bv[2], bv[3]);
            }
        }
        __syncthreads();     // all warps done with K/V before next tile load
    }

    // ---- epilogue: normalize, write O (fp16) ----
    float inv0 = 1.0f / l[0], inv1 = 1.0f / l[1];
    #pragma unroll
    for (int nv = 0; nv < 8; nv++) {
        int col = hoff + nv * 8 + 2 * j;
        long row = qrow0 + w * 16 + r4;
        *(uint32_t*)&Og[row * ED_ + col]       = pack2h(accO[nv][0] * inv0, accO[nv][1] * inv0);
        *(uint32_t*)&Og[(row + 8) * ED_ + col] = pack2h(accO[nv][2] * inv1, accO[nv][3] * inv1);
    }
}

// ----------------------------------------------------------------------------
// Host orchestration
// ----------------------------------------------------------------------------
extern "C" void kernel_launch(void* const* d_in, const int* in_sizes, int n_in,
                              void* d_out, int out_size) {
    const float* x     = (const float*)d_in[0];
    const float* enc   = (const float*)d_in[1];
    // d_in[2] = tgt_mask (always causal tril; handled analytically)
    const float* sa_wq = (const float*)d_in[3];
    const float* sa_bq = (const float*)d_in[4];
    const float* sa_wk = (const float*)d_in[5];
    const float* sa_bk = (const float*)d_in[6];
    const float* sa_wv = (const float*)d_in[7];
    const float* sa_bv = (const float*)d_in[8];
    const float* sa_wo = (const float*)d_in[9];
    const float* sa_bo = (const float*)d_in[10];
    const float* ca_wq = (const float*)d_in[11];
    const float* ca_bq = (const float*)d_in[12];
    const float* ca_wk = (const float*)d_in[13];
    const float* ca_bk = (const float*)d_in[14];
    const float* ca_wv = (const float*)d_in[15];
    const float* ca_bv = (const float*)d_in[16];
    const float* ca_wo = (const float*)d_in[17];
    const float* ca_bo = (const float*)d_in[18];
    const float* ff_w1 = (const float*)d_in[19];
    const float* ff_b1 = (const float*)d_in[20];
    const float* ff_w2 = (const float*)d_in[21];
    const float* ff_b2 = (const float*)d_in[22];
    const float* ln1g  = (const float*)d_in[23];
    const float* ln1b  = (const float*)d_in[24];
    const float* ln2g  = (const float*)d_in[25];
    const float* ln2b  = (const float*)d_in[26];
    const float* ln3g  = (const float*)d_in[27];
    const float* ln3b  = (const float*)d_in[28];
    float* out = (float*)d_out;

    __half *Hh, *Qh, *Kh, *Vh, *Ah, *F1h, *encH, *W16;
    float  *X1;
    cudaGetSymbolAddress((void**)&Hh,   g_Hh);
    cudaGetSymbolAddress((void**)&Qh,   g_Qh);
    cudaGetSymbolAddress((void**)&Kh,   g_Kh);
    cudaGetSymbolAddress((void**)&Vh,   g_Vh);
    cudaGetSymbolAddress((void**)&Ah,   g_Ah);
    cudaGetSymbolAddress((void**)&F1h,  g_F1h);
    cudaGetSymbolAddress((void**)&encH, g_encH);
    cudaGetSymbolAddress((void**)&W16,  g_W16);
    cudaGetSymbolAddress((void**)&X1,   g_X1);

    const float qscale = 0.125f;        // 1/sqrt(64) folded into Q projection
    const int gW1M = (ED_ * ED_) / 2048;    // 512 blocks (1M elems)
    const int gW4M = (ED_ * FF_) / 2048;    // 2048 blocks (4M elems)

    dim3 gP(ED_ / 128, BT_ / 128);          // (8, 32)
    dim3 gF1(FF_ / 128, BT_ / 128);         // (32, 32)
    dim3 gFlash(T_ / 128, NH_, B_);         // (16, 16, 2)

    // encoder outputs -> fp16 (used by both CA K and V projections)
    f2h_k<<<gW4M, 256>>>(enc, encH);

    // ---------------- self-attention block ----------------
    ln_k<<<BT_, 256>>>(x, ln1g, ln1b, Hh);
    f2h_k<<<gW1M, 256>>>(sa_wq, W16);
    hgemm<false, false, true><<<gP, 256>>>(Hh, W16, sa_bq, nullptr, nullptr, Qh, ED_, ED_, qscale);
    f2h_k<<<gW1M, 256>>>(sa_wk, W16);
    hgemm<false, false, true><<<gP, 256>>>(Hh, W16, sa_bk, nullptr, nullptr, Kh, ED_, ED_, 1.0f);
    f2h_k<<<gW1M, 256>>>(sa_wv, W16);
    hgemm<false, false, true><<<gP, 256>>>(Hh, W16, sa_bv, nullptr, nullptr, Vh, ED_, ED_, 1.0f);
    hflash<true><<<gFlash, 256>>>(Qh, Kh, Vh, Ah);
    f2h_k<<<gW1M, 256>>>(sa_wo, W16);
    hgemm<false, true, false><<<gP, 256>>>(Ah, W16, sa_bo, x, X1, nullptr, ED_, ED_, 1.0f);

    // ---------------- cross-attention block ----------------
    ln_k<<<BT_, 256>>>(X1, ln2g, ln2b, Hh);
    f2h_k<<<gW1M, 256>>>(ca_wq, W16);
    hgemm<false, false, true><<<gP, 256>>>(Hh, W16, ca_bq, nullptr, nullptr, Qh, ED_, ED_, qscale);
    f2h_k<<<gW1M, 256>>>(ca_wk, W16);
    hgemm<false, false, true><<<gP, 256>>>(encH, W16, ca_bk, nullptr, nullptr, Kh, ED_, ED_, 1.0f);
    f2h_k<<<gW1M, 256>>>(ca_wv, W16);
    hgemm<false, false, true><<<gP, 256>>>(encH, W16, ca_bv, nullptr, nullptr, Vh, ED_, ED_, 1.0f);
    hflash<false><<<gFlash, 256>>>(Qh, Kh, Vh, Ah);
    f2h_k<<<gW1M, 256>>>(ca_wo, W16);
    hgemm<false, true, false><<<gP, 256>>>(Ah, W16, ca_bo, X1, out, nullptr, ED_, ED_, 1.0f);

    // ---------------- feed-forward block ----------------
    ln_k<<<BT_, 256>>>(out, ln3g, ln3b, Hh);
    f2h_k<<<gW4M, 256>>>(ff_w1, W16);
    hgemm<true, false, true><<<gF1, 256>>>(Hh, W16, ff_b1, nullptr, nullptr, F1h, ED_, FF_, 1.0f);
    f2h_k<<<gW4M, 256>>>(ff_w2, W16);
    hgemm<false, true, false><<<gP, 256>>>(F1h, W16, ff_b2, out, out, nullptr, FF_, ED_, 1.0f);
}